// round 14
// baseline (speedup 1.0000x reference)
#include <cuda_runtime.h>

// RK4 over f(y) = tanh(y@W1+b1)@W2 + b2.  S*B=3072 rows, D=32, H=128, T=256.
//
// R14 = R13 (2532us) with three MIO-path cuts, all bitwise-identical math
// (commutativity of FADD only -> rel_err must stay exactly 7.949753e-07):
//  (i)  pass-A stage-2 exchange is a SCALAR shfl (send only the component
//       the partner pair needs): -16 SASS SHFL/feval.
//  (ii) g-reduce as reduce-scatter(^1 on row-halves) -> all-reduce(^2,^4 on
//       8 ull) -> allgather(^1): 96 -> 64 SASS SHFL, -24 add2, +SELs (ALU).
//  (iii) b1 values preloaded into 16 registers (loop-invariant):
//       -16 scalar LDS/feval.
// Layout unchanged: lane=(g=lane&7, s=lane>>3); lane owns j=g+8i and state
// quarter [8s..8s+7]; warp carries 4 rows, autonomous; NC=6 W2 planes in
// registers; phase-split feval; single-copy RK4 substep loop.

#define DIM   32
#define HID   128
#define NT    256
#define NROWS 3072
#define TPB   64
#define RPW   4                    // rows per warp
#define RPB   ((TPB/32)*RPW)       // 8 rows per block
#define NBLK  (NROWS/RPB)          // 384
#define NC    6                    // W2 planes cached in registers

typedef unsigned long long ull;

__device__ __forceinline__ ull fma2(ull a, ull b, ull c) {
    ull d;
    asm("fma.rn.f32x2 %0, %1, %2, %3;" : "=l"(d) : "l"(a), "l"(b), "l"(c));
    return d;
}
__device__ __forceinline__ ull add2(ull a, ull b) {
    ull d;
    asm("add.rn.f32x2 %0, %1, %2;" : "=l"(d) : "l"(a), "l"(b));
    return d;
}
__device__ __forceinline__ ull pack2(float lo, float hi) {
    ull d;
    asm("mov.b64 %0, {%1, %2};" : "=l"(d) : "f"(lo), "f"(hi));
    return d;
}
__device__ __forceinline__ void unpack2(ull v, float& lo, float& hi) {
    asm("mov.b64 {%0, %1}, %2;" : "=f"(lo), "=f"(hi) : "l"(v));
}

// accurate fast tanh: 1 - 2/(exp(2x)+1); ~1e-7 abs err, saturates at +/-inf.
__device__ __forceinline__ float tanh_fast(float x) {
    float e = __expf(2.0f * x);
    return 1.0f - __fdividef(2.0f, e + 1.0f);
}

// Half of one f evaluation (8 i-planes starting at BASE) for the warp's 4
// rows. Pass A: dots + (2 packed ^8 + 1 scalar ^16) reduce -> stage fs.
// Pass B: tanh + 2-shfl rebroadcast + scatter (W2 regs when BASE==0,ii<NC).
template<int BASE>
__device__ __forceinline__ void feval_half(
    const ull in[RPW][4], ull kq[RPW][4],
    const ulonglong2* __restrict__ w1aL, const ulonglong2* __restrict__ w1bL,
    const ulonglong2* __restrict__ w2aL, const ulonglong2* __restrict__ w2bL,
    const ulonglong2 (&vaR)[NC], const ulonglong2 (&vbR)[NC],
    const float (&b1R)[16], int s)
{
    const bool sLo = (s & 1) != 0;   // position within s-pair
    const bool sHi = (s & 2) != 0;   // which s-pair (-> which row-pair I own)

    const ulonglong2* waP = w1aL + BASE * 32;
    const ulonglong2* wbP = w1bL + BASE * 32;
    const ulonglong2* vaP = w2aL + BASE * 32;
    const ulonglong2* vbP = w2bL + BASE * 32;

    // ---- pass A: dots + reduce; stage pre-tanh scalars (8 regs) ----
    float fsst[8];
#pragma unroll
    for (int ii = 0; ii < 8; ++ii) {
        const ulonglong2 wa = waP[ii * 32];   // W1[8s+0..3 , j]
        const ulonglong2 wb = wbP[ii * 32];   // W1[8s+4..7 , j]

        float hs[RPW];
#pragma unroll
        for (int r = 0; r < RPW; ++r) {
            ull t0 = fma2(in[r][0], wa.x, 0ull);
            ull t1 = fma2(in[r][2], wb.x, 0ull);
            t0 = fma2(in[r][1], wa.y, t0);
            t1 = fma2(in[r][3], wb.y, t1);
            float lo, hi;
            unpack2(add2(t0, t1), lo, hi);
            hs[r] = lo + hi;
        }

        // stage 1: reduce over s-pair (^8); 2 rows per packed value
        ull q01 = pack2(hs[0], hs[1]);
        ull q23 = pack2(hs[2], hs[3]);
        q01 = add2(q01, __shfl_xor_sync(0xffffffffu, q01, 8));
        q23 = add2(q23, __shfl_xor_sync(0xffffffffu, q23, 8));
        // stage 2: SCALAR ^16 exchange — send exactly the component the
        // partner pair needs (its row = s^2, component s&1 of my other pair)
        float a0, a1, b0, b1v;
        unpack2(q01, a0, a1);
        unpack2(q23, b0, b1v);
        const float mine = sHi ? (sLo ? b1v : b0) : (sLo ? a1 : a0);
        const float send = sHi ? (sLo ? a1 : a0) : (sLo ? b1v : b0);
        const float recv = __shfl_xor_sync(0xffffffffu, send, 16);
        fsst[ii] = (mine + recv) + b1R[BASE + ii];   // my row's pre-tanh
    }

    // ---- pass B: tanh + rebroadcast + scatter ----
#pragma unroll
    for (int ii = 0; ii < 8; ++ii) {
        const float h = tanh_fast(fsst[ii]);          // row s's h only
        // rebroadcast 4 h's: ^8 (scalar) then ^16 (packed)
        const float ho = __shfl_xor_sync(0xffffffffu, h, 8);
        const float hl = sLo ? ho : h;
        const float hu = sLo ? h : ho;
        const ull hp = pack2(hl, hu);
        const ull hq = __shfl_xor_sync(0xffffffffu, hp, 16);
        const ull h01 = sHi ? hq : hp;   // (h0, h1)
        const ull h23 = sHi ? hp : hq;   // (h2, h3)
        float h0, h1, h2, h3;
        unpack2(h01, h0, h1);
        unpack2(h23, h2, h3);
        ull hhr[RPW];
        hhr[0] = pack2(h0, h0);
        hhr[1] = pack2(h1, h1);
        hhr[2] = pack2(h2, h2);
        hhr[3] = pack2(h3, h3);

        const bool useR = (BASE == 0) && (ii < NC);
        const ulonglong2 va = useR ? vaR[ii < NC ? ii : 0] : vaP[ii * 32];
        const ulonglong2 vb = useR ? vbR[ii < NC ? ii : 0] : vbP[ii * 32];
#pragma unroll
        for (int r = 0; r < RPW; ++r) {
            kq[r][0] = fma2(hhr[r], va.x, kq[r][0]);
            kq[r][1] = fma2(hhr[r], va.y, kq[r][1]);
            kq[r][2] = fma2(hhr[r], vb.x, kq[r][2]);
            kq[r][3] = fma2(hhr[r], vb.y, kq[r][3]);
        }
    }
}

// One f evaluation for the warp's 4 rows.
__device__ __forceinline__ void feval(
    const ull in[RPW][4], ull kq[RPW][4],
    const ulonglong2* __restrict__ w1aL, const ulonglong2* __restrict__ w1bL,
    const ulonglong2* __restrict__ w2aL, const ulonglong2* __restrict__ w2bL,
    const ulonglong2 (&vaR)[NC], const ulonglong2 (&vbR)[NC],
    const float (&b1R)[16], const ull b2q[4], int g, int s)
{
#pragma unroll
    for (int r = 0; r < RPW; ++r)
#pragma unroll
        for (int d = 0; d < 4; ++d) kq[r][d] = 0ull;

    feval_half<0>(in, kq, w1aL, w1bL, w2aL, w2bL, vaR, vbR, b1R, s);
    feval_half<8>(in, kq, w1aL, w1bL, w2aL, w2bL, vaR, vbR, b1R, s);

    // ---- g-reduce: reduce-scatter(^1) -> all-reduce(^2,^4) -> allgather(^1)
    // Even g keeps rows{0,1}-half, odd keeps rows{2,3}-half. Bitwise equal
    // to the old 3-round all-reduce (FADD commutativity only).
    const bool gOdd = (g & 1) != 0;
    ull p[8];
#pragma unroll
    for (int j = 0; j < 8; ++j) {
        const int r = j >> 2, d = j & 3;
        const ull sendv = gOdd ? kq[r][d] : kq[2 + r][d];   // give away other half
        const ull recvv = __shfl_xor_sync(0xffffffffu, sendv, 1);
        const ull minev = gOdd ? kq[2 + r][d] : kq[r][d];
        p[j] = add2(minev, recvv);
    }
#pragma unroll
    for (int j = 0; j < 8; ++j)
        p[j] = add2(p[j], __shfl_xor_sync(0xffffffffu, p[j], 2));
#pragma unroll
    for (int j = 0; j < 8; ++j)
        p[j] = add2(p[j], __shfl_xor_sync(0xffffffffu, p[j], 4));
#pragma unroll
    for (int j = 0; j < 8; ++j) {
        const int r = j >> 2, d = j & 3;
        const ull q = __shfl_xor_sync(0xffffffffu, p[j], 1);
        kq[r][d]     = gOdd ? q    : p[j];   // rows{0,1} total
        kq[2 + r][d] = gOdd ? p[j] : q;      // rows{2,3} total
    }

#pragma unroll
    for (int r = 0; r < RPW; ++r)
#pragma unroll
        for (int d = 0; d < 4; ++d) kq[r][d] = add2(kq[r][d], b2q[d]);
}

__global__ __launch_bounds__(TPB)
void rk4_mlp_kernel(
    const float* __restrict__ first_point,   // [3072, 32]
    const float* __restrict__ time_steps,    // [256]
    const float* __restrict__ W1,            // [32, 128]
    const float* __restrict__ b1,            // [128]
    const float* __restrict__ W2,            // [128, 32]
    const float* __restrict__ b2,            // [32]
    float* __restrict__ out)                 // [3072, 256, 32]
{
    // weight packs: [i][lane]; every warp LDS.128 is 512B all-unique
    __shared__ ulonglong2 w1qA[16][32];  // float4 = W1[8s+0..3 , g+8i]
    __shared__ ulonglong2 w1qB[16][32];  // float4 = W1[8s+4..7 , g+8i]
    __shared__ ulonglong2 w2qA[16][32];  // float4 = W2[g+8i][8s+0..3]
    __shared__ ulonglong2 w2qB[16][32];  // float4 = W2[g+8i][8s+4..7]
    __shared__ float b1s[HID];
    __shared__ float tss[NT];

    const int tid = threadIdx.x;

    // ---- stage weights (one-time; scalar writes) ----
    {
        float* a1 = (float*)w1qA; float* a2 = (float*)w1qB;
        float* a3 = (float*)w2qA; float* a4 = (float*)w2qB;
        for (int idx = tid; idx < 16 * 32 * 4; idx += TPB) {
            const int i  = idx >> 7;          // plane
            const int ln = (idx >> 2) & 31;   // lane
            const int f  = idx & 3;           // float within float4
            const int ss = ln >> 3, gg = ln & 7;
            const int j  = gg + 8 * i;
            a1[idx] = W1[(8 * ss + f)     * HID + j];
            a2[idx] = W1[(8 * ss + 4 + f) * HID + j];
            a3[idx] = W2[j * DIM + 8 * ss + f];
            a4[idx] = W2[j * DIM + 8 * ss + 4 + f];
        }
        for (int idx = tid; idx < HID; idx += TPB) b1s[idx] = b1[idx];
        for (int idx = tid; idx < NT;  idx += TPB) tss[idx] = time_steps[idx];
    }
    __syncthreads();

    const int lane = tid & 31;
    const int warp = tid >> 5;
    const int g = lane & 7;
    const int s = lane >> 3;
    const int rbase = blockIdx.x * RPB + warp * RPW;

    const ulonglong2* w1aL = &w1qA[0][lane];
    const ulonglong2* w1bL = &w1qB[0][lane];
    const ulonglong2* w2aL = &w2qA[0][lane];
    const ulonglong2* w2bL = &w2qB[0][lane];

    // W2 planes 0..NC-1 resident in registers (reused 4080x)
    ulonglong2 vaR[NC], vbR[NC];
#pragma unroll
    for (int p = 0; p < NC; ++p) {
        vaR[p] = w2aL[p * 32];
        vbR[p] = w2bL[p * 32];
    }

    // b1 values for this lane's hidden units, in registers (loop-invariant)
    float b1R[16];
#pragma unroll
    for (int i = 0; i < 16; ++i) b1R[i] = b1s[g + 8 * i];

    // b2 quarter, packed (registers)
    ull b2q[4];
#pragma unroll
    for (int d = 0; d < 4; ++d)
        b2q[d] = pack2(b2[8 * s + 2 * d], b2[8 * s + 2 * d + 1]);

    // ---- load initial state: lane's quarter for each of 4 rows ----
    ull y2[RPW][4], acc2[RPW][4], yin2[RPW][4], k2[RPW][4];
#pragma unroll
    for (int r = 0; r < RPW; ++r) {
        const ulonglong2* fp = reinterpret_cast<const ulonglong2*>(
            first_point + (size_t)(rbase + r) * DIM + 8 * s);
        ulonglong2 v0 = fp[0], v1 = fp[1];
        y2[r][0] = v0.x; y2[r][1] = v0.y;
        y2[r][2] = v1.x; y2[r][3] = v1.y;
    }

    // t = 0: lanes g<4 write row g's quarter (coalesced 128B per row)
    if (g < 4) {
        float* dst = out + (size_t)(rbase + g) * (NT * DIM) + 8 * s;
        ulonglong2 v0, v1;
        v0.x = y2[g][0]; v0.y = y2[g][1];
        v1.x = y2[g][2]; v1.y = y2[g][3];
        reinterpret_cast<ulonglong2*>(dst)[0] = v0;
        reinterpret_cast<ulonglong2*>(dst)[1] = v1;
    }

#pragma unroll
    for (int r = 0; r < RPW; ++r)
#pragma unroll
        for (int d = 0; d < 4; ++d) yin2[r][d] = y2[r][d];

    // ---- RK4 time loop: 4 substeps, feval emitted ONCE ----
#pragma unroll 1
    for (int t = 0; t < NT - 1; ++t) {
        const float dt   = tss[t + 1] - tss[t];
        const float dt6f = dt * (1.0f / 6.0f);
        const float dt3f = dt * (1.0f / 3.0f);
        const float dthf = 0.5f * dt;

        // acc starts at y
#pragma unroll
        for (int r = 0; r < RPW; ++r)
#pragma unroll
            for (int d = 0; d < 4; ++d) acc2[r][d] = y2[r][d];

#pragma unroll 1
        for (int sub = 0; sub < 4; ++sub) {
            feval(yin2, k2, w1aL, w1bL, w2aL, w2bL, vaR, vbR, b1R, b2q, g, s);

            const float cAf = (sub == 0 || sub == 3) ? dt6f : dt3f;
            const ull cA = pack2(cAf, cAf);

            if (sub < 3) {
                const float cBf = (sub < 2) ? dthf : dt;
                const ull cB = pack2(cBf, cBf);
#pragma unroll
                for (int r = 0; r < RPW; ++r)
#pragma unroll
                    for (int d = 0; d < 4; ++d) {
                        acc2[r][d] = fma2(cA, k2[r][d], acc2[r][d]);
                        yin2[r][d] = fma2(cB, k2[r][d], y2[r][d]);
                    }
            } else {
                // finalize y_{t+1}, reset yin, store
#pragma unroll
                for (int r = 0; r < RPW; ++r)
#pragma unroll
                    for (int d = 0; d < 4; ++d) {
                        y2[r][d] = fma2(cA, k2[r][d], acc2[r][d]);
                        yin2[r][d] = y2[r][d];
                    }
                if (g < 4) {
                    float* dst = out + (size_t)(rbase + g) * (NT * DIM)
                               + (size_t)(t + 1) * DIM + 8 * s;
                    ulonglong2 v0, v1;
                    v0.x = y2[g][0]; v0.y = y2[g][1];
                    v1.x = y2[g][2]; v1.y = y2[g][3];
                    reinterpret_cast<ulonglong2*>(dst)[0] = v0;
                    reinterpret_cast<ulonglong2*>(dst)[1] = v1;
                }
            }
        }
    }
}

extern "C" void kernel_launch(void* const* d_in, const int* in_sizes, int n_in,
                              void* d_out, int out_size) {
    const float* first_point = (const float*)d_in[0];  // [3,1024,32]
    const float* time_steps  = (const float*)d_in[1];  // [256]
    const float* W1          = (const float*)d_in[2];  // [32,128]
    const float* b1          = (const float*)d_in[3];  // [128]
    const float* W2          = (const float*)d_in[4];  // [128,32]
    const float* b2          = (const float*)d_in[5];  // [32]
    float* out = (float*)d_out;                        // [3,1024,256,32]

    rk4_mlp_kernel<<<NBLK, TPB>>>(first_point, time_steps, W1, b1, W2, b2, out);
}

// round 15
// speedup vs baseline: 1.0694x; 1.0694x over previous
#include <cuda_runtime.h>

// RK4 over f(y) = tanh(y@W1+b1)@W2 + b2.  S*B=3072 rows, D=32, H=128, T=256.
//
// R15 = R13 (2532us; best) with:
//  (a) halves MERGED: one 16-wide pass A (dots + reduce -> 16 scalar fs
//      staged; kq NOT live), then one 16-wide pass B (tanh + rebroadcast +
//      scatter). Doubles the independent-chain window per pass and halves
//      the feval critical path vs two sequential 8-wide halves.
//  (b) scalar ^16 stage-2 exchange (from R14, reg-neutral): -16 SHFL/feval.
//  Reverted from R14: g-reduce restructure and b1R (both caused the 255-reg
//  cap / spills). g-reduce is R13's 3-round packed butterfly; b1 from smem.
// Layout: lane=(g=lane&7, s=lane>>3); lane owns j=g+8i and state quarter
// [8s..8s+7]; warp carries 4 rows, autonomous; NC=6 W2 planes in registers.

#define DIM   32
#define HID   128
#define NT    256
#define NROWS 3072
#define TPB   64
#define RPW   4                    // rows per warp
#define RPB   ((TPB/32)*RPW)       // 8 rows per block
#define NBLK  (NROWS/RPB)          // 384
#define NC    6                    // W2 planes cached in registers

typedef unsigned long long ull;

__device__ __forceinline__ ull fma2(ull a, ull b, ull c) {
    ull d;
    asm("fma.rn.f32x2 %0, %1, %2, %3;" : "=l"(d) : "l"(a), "l"(b), "l"(c));
    return d;
}
__device__ __forceinline__ ull add2(ull a, ull b) {
    ull d;
    asm("add.rn.f32x2 %0, %1, %2;" : "=l"(d) : "l"(a), "l"(b));
    return d;
}
__device__ __forceinline__ ull pack2(float lo, float hi) {
    ull d;
    asm("mov.b64 %0, {%1, %2};" : "=l"(d) : "f"(lo), "f"(hi));
    return d;
}
__device__ __forceinline__ void unpack2(ull v, float& lo, float& hi) {
    asm("mov.b64 {%0, %1}, %2;" : "=f"(lo), "=f"(hi) : "l"(v));
}

// accurate fast tanh: 1 - 2/(exp(2x)+1); ~1e-7 abs err, saturates at +/-inf.
__device__ __forceinline__ float tanh_fast(float x) {
    float e = __expf(2.0f * x);
    return 1.0f - __fdividef(2.0f, e + 1.0f);
}

// One f evaluation for the warp's 4 rows.  in/kq: [row][quarter-f32x2].
__device__ __forceinline__ void feval(
    const ull in[RPW][4], ull kq[RPW][4],
    const ulonglong2* __restrict__ w1aL, const ulonglong2* __restrict__ w1bL,
    const ulonglong2* __restrict__ w2aL, const ulonglong2* __restrict__ w2bL,
    const ulonglong2 (&vaR)[NC], const ulonglong2 (&vbR)[NC],
    const float* __restrict__ b1L, const ull b2q[4], int s)
{
    const bool sLo = (s & 1) != 0;   // position within s-pair
    const bool sHi = (s & 2) != 0;   // which s-pair (-> which row-pair I own)

    // ---- pass A: 16-wide dots + reduce; stage pre-tanh scalars ----
    // kq is NOT live here -> register peak stays manageable.
    float fsst[16];
#pragma unroll
    for (int ii = 0; ii < 16; ++ii) {
        const ulonglong2 wa = w1aL[ii * 32];   // W1[8s+0..3 , j]
        const ulonglong2 wb = w1bL[ii * 32];   // W1[8s+4..7 , j]

        float hs[RPW];
#pragma unroll
        for (int r = 0; r < RPW; ++r) {
            ull t0 = fma2(in[r][0], wa.x, 0ull);
            ull t1 = fma2(in[r][2], wb.x, 0ull);
            t0 = fma2(in[r][1], wa.y, t0);
            t1 = fma2(in[r][3], wb.y, t1);
            float lo, hi;
            unpack2(add2(t0, t1), lo, hi);
            hs[r] = lo + hi;
        }

        // stage 1: reduce over s-pair (^8); 2 rows per packed value
        ull q01 = pack2(hs[0], hs[1]);
        ull q23 = pack2(hs[2], hs[3]);
        q01 = add2(q01, __shfl_xor_sync(0xffffffffu, q01, 8));
        q23 = add2(q23, __shfl_xor_sync(0xffffffffu, q23, 8));
        // stage 2: SCALAR ^16 exchange — send exactly the component the
        // partner pair needs; receive my row's missing partial.
        float a0, a1, b0v, b1v;
        unpack2(q01, a0, a1);
        unpack2(q23, b0v, b1v);
        const float mine = sHi ? (sLo ? b1v : b0v) : (sLo ? a1 : a0);
        const float send = sHi ? (sLo ? a1 : a0) : (sLo ? b1v : b0v);
        const float recv = __shfl_xor_sync(0xffffffffu, send, 16);
        fsst[ii] = (mine + recv) + b1L[8 * ii];   // my row's pre-tanh
    }

    // ---- pass B: 16-wide tanh + rebroadcast + scatter ----
#pragma unroll
    for (int r = 0; r < RPW; ++r)
#pragma unroll
        for (int d = 0; d < 4; ++d) kq[r][d] = 0ull;

#pragma unroll
    for (int ii = 0; ii < 16; ++ii) {
        const float h = tanh_fast(fsst[ii]);          // row s's h only
        // rebroadcast 4 h's: ^8 (scalar) then ^16 (packed)
        const float ho = __shfl_xor_sync(0xffffffffu, h, 8);
        const float hl = sLo ? ho : h;
        const float hu = sLo ? h : ho;
        const ull hp = pack2(hl, hu);
        const ull hq = __shfl_xor_sync(0xffffffffu, hp, 16);
        const ull h01 = sHi ? hq : hp;   // (h0, h1)
        const ull h23 = sHi ? hp : hq;   // (h2, h3)
        float h0, h1, h2, h3;
        unpack2(h01, h0, h1);
        unpack2(h23, h2, h3);
        ull hhr[RPW];
        hhr[0] = pack2(h0, h0);
        hhr[1] = pack2(h1, h1);
        hhr[2] = pack2(h2, h2);
        hhr[3] = pack2(h3, h3);

        const ulonglong2 va = (ii < NC) ? vaR[ii < NC ? ii : 0]
                                        : w2aL[ii * 32];
        const ulonglong2 vb = (ii < NC) ? vbR[ii < NC ? ii : 0]
                                        : w2bL[ii * 32];
#pragma unroll
        for (int r = 0; r < RPW; ++r) {
            kq[r][0] = fma2(hhr[r], va.x, kq[r][0]);
            kq[r][1] = fma2(hhr[r], va.y, kq[r][1]);
            kq[r][2] = fma2(hhr[r], vb.x, kq[r][2]);
            kq[r][3] = fma2(hhr[r], vb.y, kq[r][3]);
        }
    }

    // reduce partial k over the 8 g-lanes (lanes ^1, ^2, ^4), then + b2
#pragma unroll
    for (int m = 1; m < 8; m <<= 1) {
#pragma unroll
        for (int r = 0; r < RPW; ++r)
#pragma unroll
            for (int d = 0; d < 4; ++d)
                kq[r][d] = add2(kq[r][d],
                                __shfl_xor_sync(0xffffffffu, kq[r][d], m));
    }
#pragma unroll
    for (int r = 0; r < RPW; ++r)
#pragma unroll
        for (int d = 0; d < 4; ++d) kq[r][d] = add2(kq[r][d], b2q[d]);
}

__global__ __launch_bounds__(TPB)
void rk4_mlp_kernel(
    const float* __restrict__ first_point,   // [3072, 32]
    const float* __restrict__ time_steps,    // [256]
    const float* __restrict__ W1,            // [32, 128]
    const float* __restrict__ b1,            // [128]
    const float* __restrict__ W2,            // [128, 32]
    const float* __restrict__ b2,            // [32]
    float* __restrict__ out)                 // [3072, 256, 32]
{
    // weight packs: [i][lane]; every warp LDS.128 is 512B all-unique
    __shared__ ulonglong2 w1qA[16][32];  // float4 = W1[8s+0..3 , g+8i]
    __shared__ ulonglong2 w1qB[16][32];  // float4 = W1[8s+4..7 , g+8i]
    __shared__ ulonglong2 w2qA[16][32];  // float4 = W2[g+8i][8s+0..3]
    __shared__ ulonglong2 w2qB[16][32];  // float4 = W2[g+8i][8s+4..7]
    __shared__ float b1s[HID];
    __shared__ float tss[NT];

    const int tid = threadIdx.x;

    // ---- stage weights (one-time; scalar writes) ----
    {
        float* a1 = (float*)w1qA; float* a2 = (float*)w1qB;
        float* a3 = (float*)w2qA; float* a4 = (float*)w2qB;
        for (int idx = tid; idx < 16 * 32 * 4; idx += TPB) {
            const int i  = idx >> 7;          // plane
            const int ln = (idx >> 2) & 31;   // lane
            const int f  = idx & 3;           // float within float4
            const int ss = ln >> 3, gg = ln & 7;
            const int j  = gg + 8 * i;
            a1[idx] = W1[(8 * ss + f)     * HID + j];
            a2[idx] = W1[(8 * ss + 4 + f) * HID + j];
            a3[idx] = W2[j * DIM + 8 * ss + f];
            a4[idx] = W2[j * DIM + 8 * ss + 4 + f];
        }
        for (int idx = tid; idx < HID; idx += TPB) b1s[idx] = b1[idx];
        for (int idx = tid; idx < NT;  idx += TPB) tss[idx] = time_steps[idx];
    }
    __syncthreads();

    const int lane = tid & 31;
    const int warp = tid >> 5;
    const int g = lane & 7;
    const int s = lane >> 3;
    const int rbase = blockIdx.x * RPB + warp * RPW;

    const ulonglong2* w1aL = &w1qA[0][lane];
    const ulonglong2* w1bL = &w1qB[0][lane];
    const ulonglong2* w2aL = &w2qA[0][lane];
    const ulonglong2* w2bL = &w2qB[0][lane];
    const float* b1L = b1s + g;

    // W2 planes 0..NC-1 resident in registers (reused 4080x)
    ulonglong2 vaR[NC], vbR[NC];
#pragma unroll
    for (int p = 0; p < NC; ++p) {
        vaR[p] = w2aL[p * 32];
        vbR[p] = w2bL[p * 32];
    }

    // b2 quarter, packed (registers)
    ull b2q[4];
#pragma unroll
    for (int d = 0; d < 4; ++d)
        b2q[d] = pack2(b2[8 * s + 2 * d], b2[8 * s + 2 * d + 1]);

    // ---- load initial state: lane's quarter for each of 4 rows ----
    ull y2[RPW][4], acc2[RPW][4], yin2[RPW][4], k2[RPW][4];
#pragma unroll
    for (int r = 0; r < RPW; ++r) {
        const ulonglong2* fp = reinterpret_cast<const ulonglong2*>(
            first_point + (size_t)(rbase + r) * DIM + 8 * s);
        ulonglong2 v0 = fp[0], v1 = fp[1];
        y2[r][0] = v0.x; y2[r][1] = v0.y;
        y2[r][2] = v1.x; y2[r][3] = v1.y;
    }

    // t = 0: lanes g<4 write row g's quarter (coalesced 128B per row)
    if (g < 4) {
        float* dst = out + (size_t)(rbase + g) * (NT * DIM) + 8 * s;
        ulonglong2 v0, v1;
        v0.x = y2[g][0]; v0.y = y2[g][1];
        v1.x = y2[g][2]; v1.y = y2[g][3];
        reinterpret_cast<ulonglong2*>(dst)[0] = v0;
        reinterpret_cast<ulonglong2*>(dst)[1] = v1;
    }

#pragma unroll
    for (int r = 0; r < RPW; ++r)
#pragma unroll
        for (int d = 0; d < 4; ++d) yin2[r][d] = y2[r][d];

    // ---- RK4 time loop: 4 substeps, feval emitted ONCE ----
#pragma unroll 1
    for (int t = 0; t < NT - 1; ++t) {
        const float dt   = tss[t + 1] - tss[t];
        const float dt6f = dt * (1.0f / 6.0f);
        const float dt3f = dt * (1.0f / 3.0f);
        const float dthf = 0.5f * dt;

        // acc starts at y
#pragma unroll
        for (int r = 0; r < RPW; ++r)
#pragma unroll
            for (int d = 0; d < 4; ++d) acc2[r][d] = y2[r][d];

#pragma unroll 1
        for (int sub = 0; sub < 4; ++sub) {
            feval(yin2, k2, w1aL, w1bL, w2aL, w2bL, vaR, vbR, b1L, b2q, s);

            const float cAf = (sub == 0 || sub == 3) ? dt6f : dt3f;
            const ull cA = pack2(cAf, cAf);

            if (sub < 3) {
                const float cBf = (sub < 2) ? dthf : dt;
                const ull cB = pack2(cBf, cBf);
#pragma unroll
                for (int r = 0; r < RPW; ++r)
#pragma unroll
                    for (int d = 0; d < 4; ++d) {
                        acc2[r][d] = fma2(cA, k2[r][d], acc2[r][d]);
                        yin2[r][d] = fma2(cB, k2[r][d], y2[r][d]);
                    }
            } else {
                // finalize y_{t+1}, reset yin, store
#pragma unroll
                for (int r = 0; r < RPW; ++r)
#pragma unroll
                    for (int d = 0; d < 4; ++d) {
                        y2[r][d] = fma2(cA, k2[r][d], acc2[r][d]);
                        yin2[r][d] = y2[r][d];
                    }
                if (g < 4) {
                    float* dst = out + (size_t)(rbase + g) * (NT * DIM)
                               + (size_t)(t + 1) * DIM + 8 * s;
                    ulonglong2 v0, v1;
                    v0.x = y2[g][0]; v0.y = y2[g][1];
                    v1.x = y2[g][2]; v1.y = y2[g][3];
                    reinterpret_cast<ulonglong2*>(dst)[0] = v0;
                    reinterpret_cast<ulonglong2*>(dst)[1] = v1;
                }
            }
        }
    }
}

extern "C" void kernel_launch(void* const* d_in, const int* in_sizes, int n_in,
                              void* d_out, int out_size) {
    const float* first_point = (const float*)d_in[0];  // [3,1024,32]
    const float* time_steps  = (const float*)d_in[1];  // [256]
    const float* W1          = (const float*)d_in[2];  // [32,128]
    const float* b1          = (const float*)d_in[3];  // [128]
    const float* W2          = (const float*)d_in[4];  // [128,32]
    const float* b2          = (const float*)d_in[5];  // [32]
    float* out = (float*)d_out;                        // [3,1024,256,32]

    rk4_mlp_kernel<<<NBLK, TPB>>>(first_point, time_steps, W1, b1, W2, b2, out);
}